// round 6
// baseline (speedup 1.0000x reference)
#include <cuda_runtime.h>

#define NN   100000
#define NE   1600000
#define NA   1000
#define FULLMASK 0xffffffffu

// ---------------- scratch (static __device__ globals; no allocs) ----------------
__device__ __align__(16) float g_sum[NN * 32];   // per-layer neighbor-sum accumulator
__device__ __align__(16) float g_h1 [NN * 32];   // layer-1 output
__device__ __align__(16) float g_h2 [NN * 32];   // layer-2 output (only flagged rows valid)
__device__ float         g_inv[NN];              // 1 / max(indeg, 1)
__device__ int           g_cnt[NN];
__device__ unsigned char g_need[NN];             // nodes whose h2 feeds the output cone
__device__ int           g_src[NE];              // edges converted to int32
__device__ int           g_dst[NE];
__device__ int           g_is64;                 // runtime-detected edge dtype

// Explicit global-space vector reduction (generic-pointer vector atomics trap).
__device__ __forceinline__ void red_add_v4(float4* p, float4 v) {
    unsigned long long gp = __cvta_generic_to_global(p);
    asm volatile("red.global.add.v4.f32 [%0], {%1, %2, %3, %4};"
                 :: "l"(gp), "f"(v.x), "f"(v.y), "f"(v.z), "f"(v.w)
                 : "memory");
}

// ---------------- dtype detection (device-side, capture-safe) ----------------
// If the buffer is int32, interpreting it as int64 packs two consecutive edge
// ids per word -> values ~2^32+, far outside [0, NN). If genuinely int64, all
// values are valid node ids.
__global__ void k_detect(const void* ei) {
    const long long* p = (const long long*)ei;
    int ok = 1;
    for (int i = 0; i < 64; i++) {
        unsigned long long v = (unsigned long long)p[i];
        if (v >= (unsigned long long)NN) { ok = 0; break; }
    }
    g_is64 = ok;
}

// ---------------- init / convert / degree (single edge walk) ----------------
__global__ void k_zero_init() {
    int i = blockIdx.x * 256 + threadIdx.x;
    if (i < NN * 8) reinterpret_cast<float4*>(g_sum)[i] = make_float4(0.f, 0.f, 0.f, 0.f);
    if (i < NN) { g_cnt[i] = 0; g_need[i] = (i < NA) ? 1 : 0; }
}

__global__ void k_zero_sum() {
    int i = blockIdx.x * 256 + threadIdx.x;
    if (i < NN * 8) reinterpret_cast<float4*>(g_sum)[i] = make_float4(0.f, 0.f, 0.f, 0.f);
}

__global__ void k_zero_sum_small() {
    int i = blockIdx.x * 256 + threadIdx.x;
    if (i < NA * 8) reinterpret_cast<float4*>(g_sum)[i] = make_float4(0.f, 0.f, 0.f, 0.f);
}

// Convert edges to int32, accumulate in-degree, and mark the layer-3 cone.
__global__ void k_convert_count(const void* ei) {
    int e = blockIdx.x * 256 + threadIdx.x;
    if (e >= NE) return;
    int src, dst;
    if (g_is64) {
        const long long* p = (const long long*)ei;
        src = (int)p[e];
        dst = (int)p[NE + e];
    } else {
        const int* p = (const int*)ei;
        src = p[e];
        dst = p[NE + e];
    }
    g_src[e] = src;
    g_dst[e] = dst;
    atomicAdd(&g_cnt[dst], 1);
    if (dst < NA) g_need[src] = 1;   // src feeds the output cone at layer 3
}

__global__ void k_inv() {
    int v = blockIdx.x * 256 + threadIdx.x;
    if (v < NN) {
        int c = g_cnt[v];
        g_inv[v] = 1.0f / (float)(c > 1 ? c : 1);
    }
}

// ---------------- scatter: sum[dst] += X[src]  (vector global reds) ----------------
// SRC: 0 = external param, 1 = g_h1, 2 = g_h2
// MODE: 0 = all edges, 1 = only need[dst], 2 = only dst < NA
template <int SRC, int MODE>
__global__ void k_scatter(const float* __restrict__ Xp) {
    int e = blockIdx.x * 256 + threadIdx.x;
    if (e >= NE) return;
    int dst = g_dst[e];
    if (MODE == 1 && !g_need[dst]) return;
    if (MODE == 2 && dst >= NA)    return;
    int src = g_src[e];
    const float* X = (SRC == 0) ? Xp : (SRC == 1 ? g_h1 : g_h2);
    const float4* xs = reinterpret_cast<const float4*>(X) + (size_t)src * 8;
    float4*       sp = reinterpret_cast<float4*>(g_sum)   + (size_t)dst * 8;
#pragma unroll
    for (int c = 0; c < 8; c++) {
        float4 v = __ldg(xs + c);
        red_add_v4(sp + c, v);
    }
}

// ---------------- node update: H = relu((sum*inv)@Wl + bl + X@Wr) ----------------
// warp-per-node; weight columns register-resident; inner product via shuffles.
template <int PRED, int SRC, int DST>
__global__ void __launch_bounds__(256) k_node(const float* __restrict__ Xp,
                                              const float* __restrict__ Wl,
                                              const float* __restrict__ bl,
                                              const float* __restrict__ Wr) {
    int lane = threadIdx.x & 31;
    int warp = (blockIdx.x * blockDim.x + threadIdx.x) >> 5;
    int nw   = (gridDim.x * blockDim.x) >> 5;

    const float* X = (SRC == 0) ? Xp : g_h1;
    float*       H = (DST == 1) ? g_h1 : g_h2;

    float wl[32], wr[32];
#pragma unroll
    for (int k = 0; k < 32; k++) { wl[k] = Wl[k * 32 + lane]; wr[k] = Wr[k * 32 + lane]; }
    float bias = bl[lane];

    for (int v = warp; v < NN; v += nw) {
        if (PRED && !g_need[v]) continue;         // warp-uniform
        float s  = g_sum[v * 32 + lane] * g_inv[v];
        float xv = X[v * 32 + lane];
        float acc = bias;
#pragma unroll
        for (int k = 0; k < 32; k++) {
            acc = fmaf(__shfl_sync(FULLMASK, s,  k), wl[k], acc);
            acc = fmaf(__shfl_sync(FULLMASK, xv, k), wr[k], acc);
        }
        H[v * 32 + lane] = fmaxf(acc, 0.0f);
    }
}

// ---------------- layer 3 node update fused with output head ----------------
__global__ void __launch_bounds__(256) k_node3_out(const float* __restrict__ Wl,
                                                   const float* __restrict__ bl,
                                                   const float* __restrict__ Wr,
                                                   const float* __restrict__ Wo,
                                                   const float* __restrict__ bo,
                                                   float* __restrict__ out) {
    int lane = threadIdx.x & 31;
    int warp = (blockIdx.x * blockDim.x + threadIdx.x) >> 5;
    int nw   = (gridDim.x * blockDim.x) >> 5;

    float wl[32], wr[32], wo[32];
#pragma unroll
    for (int k = 0; k < 32; k++) {
        wl[k] = Wl[k * 32 + lane];
        wr[k] = Wr[k * 32 + lane];
        wo[k] = Wo[k * 8 + (lane & 7)];
    }
    float bias = bl[lane];
    float bob  = bo[lane & 7];

    for (int v = warp; v < NA; v += nw) {
        float s  = g_sum[v * 32 + lane] * g_inv[v];
        float xv = g_h2 [v * 32 + lane];
        float acc = bias;
#pragma unroll
        for (int k = 0; k < 32; k++) {
            acc = fmaf(__shfl_sync(FULLMASK, s,  k), wl[k], acc);
            acc = fmaf(__shfl_sync(FULLMASK, xv, k), wr[k], acc);
        }
        float h = fmaxf(acc, 0.0f);
        float o = bob;
#pragma unroll
        for (int k = 0; k < 32; k++)
            o = fmaf(__shfl_sync(FULLMASK, h, k), wo[k], o);
        if (lane < 8) out[v * 8 + lane] = o;
    }
}

// ---------------- launch ----------------
extern "C" void kernel_launch(void* const* d_in, const int* in_sizes, int n_in,
                              void* d_out, int out_size) {
    const float* x   = (const float*)d_in[0];
    const void*  ei  = d_in[1];                 // int32 or int64, detected on device
    const float* Wl1 = (const float*)d_in[2];
    const float* bl1 = (const float*)d_in[3];
    const float* Wr1 = (const float*)d_in[4];
    const float* Wl2 = (const float*)d_in[5];
    const float* bl2 = (const float*)d_in[6];
    const float* Wr2 = (const float*)d_in[7];
    const float* Wl3 = (const float*)d_in[8];
    const float* bl3 = (const float*)d_in[9];
    const float* Wr3 = (const float*)d_in[10];
    const float* Wo  = (const float*)d_in[11];
    const float* bo  = (const float*)d_in[12];
    float* out = (float*)d_out;

    const int EB = (NE + 255) / 256;        // edge-parallel grids
    const int ZB = (NN * 8 + 255) / 256;    // zeroing grids (float4 elems)

    // dtype detect + convert + degree + cone flags (one edge walk)
    k_detect<<<1, 1>>>(ei);
    k_zero_init<<<ZB, 256>>>();
    k_convert_count<<<EB, 256>>>(ei);
    k_inv<<<(NN + 255) / 256, 256>>>();

    // layer 1: full graph
    k_scatter<0, 0><<<EB, 256>>>(x);
    k_node<0, 0, 1><<<592, 256>>>(x, Wl1, bl1, Wr1);

    // layer 2: restricted to the output cone (need[dst] edges, need[v] nodes)
    k_zero_sum<<<ZB, 256>>>();
    k_scatter<1, 1><<<EB, 256>>>(nullptr);
    k_node<1, 1, 2><<<592, 256>>>(nullptr, Wl2, bl2, Wr2);

    // layer 3 + output head: only dst < NA edges, 1000 nodes
    k_zero_sum_small<<<32, 256>>>();
    k_scatter<2, 2><<<EB, 256>>>(nullptr);
    k_node3_out<<<64, 256>>>(Wl3, bl3, Wr3, Wo, bo, out);
}

// round 8
// speedup vs baseline: 1.4248x; 1.4248x over previous
#include <cuda_runtime.h>

#define NN   100000
#define NE   1600000
#define NA   1000
#define NB   ((NN + 255) / 256)          // 391 scan blocks
#define FULLMASK 0xffffffffu

// ---------------- scratch (static __device__ globals; no allocs) ----------------
__device__ __align__(16) float g_h1 [NN * 32];   // layer-1 output (all nodes)
__device__ __align__(16) float g_h2 [NN * 32];   // layer-2 output (flagged nodes only)
__device__ float         g_inv[NN];              // 1 / max(indeg, 1)
__device__ int           g_cnt[NN];              // in-degree
__device__ int           g_off[NN];              // CSR row offsets (exclusive scan of cnt)
__device__ int           g_pos[NN];              // placement cursors
__device__ int           g_csr[NE];              // src ids grouped by dst
__device__ int           g_bsum[NB];             // scan block partials
__device__ unsigned char g_need[NN];             // nodes whose h2 feeds the output cone
__device__ int           g_nlist[NN];            // compacted list of flagged nodes
__device__ int           g_nn;                   // #flagged
__device__ int           g_is64;                 // runtime-detected edge dtype

// ---------------- dtype detection (1 warp, parallel) ----------------
// int32 buffer read as int64 packs two ids/word -> values >= 2^32 >> NN.
__global__ void k_detect(const void* ei) {
    const long long* p = (const long long*)ei;
    unsigned long long v = (unsigned long long)p[threadIdx.x];
    unsigned ok = __ballot_sync(FULLMASK, v < (unsigned long long)NN);
    if (threadIdx.x == 0) g_is64 = (ok == FULLMASK) ? 1 : 0;
}

// ---------------- init ----------------
__global__ void k_init() {
    int v = blockIdx.x * 256 + threadIdx.x;
    if (v < NN) { g_cnt[v] = 0; g_need[v] = (v < NA) ? 1 : 0; }
    if (v == 0) g_nn = 0;
}

// ---------------- count degrees + mark layer-3 cone ----------------
__global__ void k_count(const void* ei) {
    int e = blockIdx.x * 256 + threadIdx.x;
    if (e >= NE) return;
    int src, dst;
    if (g_is64) {
        const long long* p = (const long long*)ei;
        src = (int)p[e]; dst = (int)p[NE + e];
    } else {
        const int* p = (const int*)ei;
        src = p[e]; dst = p[NE + e];
    }
    atomicAdd(&g_cnt[dst], 1);
    if (dst < NA) g_need[src] = 1;
}

// ---------------- exclusive scan of g_cnt (3 kernels) ----------------
__global__ void k_scanA() {
    __shared__ int sh[256];
    int v = blockIdx.x * 256 + threadIdx.x;
    int c = (v < NN) ? g_cnt[v] : 0;
    sh[threadIdx.x] = c;
    __syncthreads();
#pragma unroll
    for (int d = 1; d < 256; d <<= 1) {
        int t = (threadIdx.x >= d) ? sh[threadIdx.x - d] : 0;
        __syncthreads();
        sh[threadIdx.x] += t;
        __syncthreads();
    }
    if (v < NN) g_off[v] = sh[threadIdx.x] - c;          // exclusive within block
    if (threadIdx.x == 255) g_bsum[blockIdx.x] = sh[255]; // block total
}

__global__ void k_scanB() {   // single block of 512, NB <= 512
    __shared__ int sh[512];
    int t = threadIdx.x;
    int c = (t < NB) ? g_bsum[t] : 0;
    sh[t] = c;
    __syncthreads();
#pragma unroll
    for (int d = 1; d < 512; d <<= 1) {
        int u = (t >= d) ? sh[t - d] : 0;
        __syncthreads();
        sh[t] += u;
        __syncthreads();
    }
    if (t < NB) g_bsum[t] = sh[t] - c;                    // exclusive block prefix
}

__global__ void k_scanC() {   // finalize offsets, cursors, inv-degree, flagged list
    int v = blockIdx.x * 256 + threadIdx.x;
    if (v >= NN) return;
    int off = g_off[v] + g_bsum[v >> 8];
    g_off[v] = off;
    g_pos[v] = off;
    int c = g_cnt[v];
    g_inv[v] = 1.0f / (float)(c > 1 ? c : 1);
    if (g_need[v]) { int i = atomicAdd(&g_nn, 1); g_nlist[i] = v; }
}

// ---------------- CSR placement ----------------
__global__ void k_place(const void* ei) {
    int e = blockIdx.x * 256 + threadIdx.x;
    if (e >= NE) return;
    int src, dst;
    if (g_is64) {
        const long long* p = (const long long*)ei;
        src = (int)p[e]; dst = (int)p[NE + e];
    } else {
        const int* p = (const int*)ei;
        src = p[e]; dst = p[NE + e];
    }
    int p_ = atomicAdd(&g_pos[dst], 1);
    g_csr[p_] = src;
}

// ---------------- fused gather + node GEMM ----------------
// Per warp: mean over CSR segment (1 feature/lane), then
// H = relu(agg@Wl + bl + X@Wr) via register-resident weights + shuffles.
__device__ __forceinline__ float gather_mean(const float* __restrict__ X,
                                             int v, int lane) {
    int beg = g_off[v], cnt = g_cnt[v];
    float acc = 0.0f;
    for (int base = 0; base < cnt; base += 32) {
        int idx = base + lane;
        int eid = (idx < cnt) ? g_csr[beg + idx] : 0;
        int n   = min(32, cnt - base);
        for (int j = 0; j < n; j++) {
            int s = __shfl_sync(FULLMASK, eid, j);
            acc += X[(size_t)s * 32 + lane];
        }
    }
    return acc * g_inv[v];
}

__device__ __forceinline__ float node_gemm(float s, float xv,
                                           const float* wl, const float* wr,
                                           float bias) {
    float acc = bias;
#pragma unroll
    for (int k = 0; k < 32; k++) {
        acc = fmaf(__shfl_sync(FULLMASK, s,  k), wl[k], acc);
        acc = fmaf(__shfl_sync(FULLMASK, xv, k), wr[k], acc);
    }
    return fmaxf(acc, 0.0f);
}

// layer 1: all nodes, X = input x, out = g_h1
__global__ void __launch_bounds__(256) k_layer1(const float* __restrict__ X,
                                                const float* __restrict__ Wl,
                                                const float* __restrict__ bl,
                                                const float* __restrict__ Wr) {
    int lane = threadIdx.x & 31;
    int warp = (blockIdx.x * blockDim.x + threadIdx.x) >> 5;
    int nw   = (gridDim.x * blockDim.x) >> 5;
    float wl[32], wr[32];
#pragma unroll
    for (int k = 0; k < 32; k++) { wl[k] = Wl[k * 32 + lane]; wr[k] = Wr[k * 32 + lane]; }
    float bias = bl[lane];
    for (int v = warp; v < NN; v += nw) {
        float s  = gather_mean(X, v, lane);
        float xv = X[(size_t)v * 32 + lane];
        g_h1[(size_t)v * 32 + lane] = node_gemm(s, xv, wl, wr, bias);
    }
}

// layer 2: flagged nodes only, X = g_h1, out = g_h2
__global__ void __launch_bounds__(256) k_layer2(const float* __restrict__ Wl,
                                                const float* __restrict__ bl,
                                                const float* __restrict__ Wr) {
    int lane = threadIdx.x & 31;
    int warp = (blockIdx.x * blockDim.x + threadIdx.x) >> 5;
    int nw   = (gridDim.x * blockDim.x) >> 5;
    float wl[32], wr[32];
#pragma unroll
    for (int k = 0; k < 32; k++) { wl[k] = Wl[k * 32 + lane]; wr[k] = Wr[k * 32 + lane]; }
    float bias = bl[lane];
    int nn = g_nn;
    for (int i = warp; i < nn; i += nw) {
        int v = g_nlist[i];
        float s  = gather_mean(g_h1, v, lane);
        float xv = g_h1[(size_t)v * 32 + lane];
        g_h2[(size_t)v * 32 + lane] = node_gemm(s, xv, wl, wr, bias);
    }
}

// layer 3 + output head: nodes [0, NA), X = g_h2
__global__ void __launch_bounds__(256) k_layer3_out(const float* __restrict__ Wl,
                                                    const float* __restrict__ bl,
                                                    const float* __restrict__ Wr,
                                                    const float* __restrict__ Wo,
                                                    const float* __restrict__ bo,
                                                    float* __restrict__ out) {
    int lane = threadIdx.x & 31;
    int warp = (blockIdx.x * blockDim.x + threadIdx.x) >> 5;
    int nw   = (gridDim.x * blockDim.x) >> 5;
    float wl[32], wr[32], wo[32];
#pragma unroll
    for (int k = 0; k < 32; k++) {
        wl[k] = Wl[k * 32 + lane];
        wr[k] = Wr[k * 32 + lane];
        wo[k] = Wo[k * 8 + (lane & 7)];
    }
    float bias = bl[lane];
    float bob  = bo[lane & 7];
    for (int v = warp; v < NA; v += nw) {
        float s  = gather_mean(g_h2, v, lane);
        float xv = g_h2[(size_t)v * 32 + lane];
        float h  = node_gemm(s, xv, wl, wr, bias);
        float o  = bob;
#pragma unroll
        for (int k = 0; k < 32; k++)
            o = fmaf(__shfl_sync(FULLMASK, h, k), wo[k], o);
        if (lane < 8) out[v * 8 + lane] = o;
    }
}

// ---------------- launch ----------------
extern "C" void kernel_launch(void* const* d_in, const int* in_sizes, int n_in,
                              void* d_out, int out_size) {
    const float* x   = (const float*)d_in[0];
    const void*  ei  = d_in[1];                 // int32 or int64, detected on device
    const float* Wl1 = (const float*)d_in[2];
    const float* bl1 = (const float*)d_in[3];
    const float* Wr1 = (const float*)d_in[4];
    const float* Wl2 = (const float*)d_in[5];
    const float* bl2 = (const float*)d_in[6];
    const float* Wr2 = (const float*)d_in[7];
    const float* Wl3 = (const float*)d_in[8];
    const float* bl3 = (const float*)d_in[9];
    const float* Wr3 = (const float*)d_in[10];
    const float* Wo  = (const float*)d_in[11];
    const float* bo  = (const float*)d_in[12];
    float* out = (float*)d_out;

    const int EB = (NE + 255) / 256;

    k_detect<<<1, 32>>>(ei);
    k_init  <<<NB, 256>>>();
    k_count <<<EB, 256>>>(ei);
    k_scanA <<<NB, 256>>>();
    k_scanB <<<1, 512>>>();
    k_scanC <<<NB, 256>>>();
    k_place <<<EB, 256>>>(ei);

    k_layer1<<<592, 256>>>(x, Wl1, bl1, Wr1);
    k_layer2<<<592, 256>>>(Wl2, bl2, Wr2);
    k_layer3_out<<<64, 256>>>(Wl3, bl3, Wr3, Wo, bo, out);
}